// round 10
// baseline (speedup 1.0000x reference)
#include <cuda_runtime.h>
#include <cuda_bf16.h>
#include <cstdint>

#define B_  4
#define T_  1024
#define D_  512
#define C_  8
#define H_  8
#define HD_ 64
#define BT_ (B_*T_)
#define TD3_ (3*D_)

// ---------------- scratch (device globals; no allocation allowed) ----------------
__device__ int   g_assign[BT_];
__device__ int   g_counts[B_*C_];
__device__ int   g_idx[B_*C_*T_];
__device__ float g_qkv[(size_t)BT_*TD3_];   // [b*T+t, 3D]  (q | k | v)
// bf16 hi/lo planes (word = bf16x2)
__device__ uint32_t g_Xh[BT_*D_/2],  g_Xl[BT_*D_/2];
__device__ uint32_t g_Wih[TD3_*D_/2], g_Wil[TD3_*D_/2];
__device__ uint32_t g_Woh[D_*D_/2],  g_Wol[D_*D_/2];
__device__ uint32_t g_Oh[BT_*D_/2],  g_Ol[BT_*D_/2];

#define MMA_BF16(d, a, b) \
    asm volatile("mma.sync.aligned.m16n8k16.row.col.f32.bf16.bf16.f32 " \
                 "{%0,%1,%2,%3},{%4,%5,%6,%7},{%8,%9},{%0,%1,%2,%3};" \
                 : "+f"((d)[0]), "+f"((d)[1]), "+f"((d)[2]), "+f"((d)[3]) \
                 : "r"((a)[0]), "r"((a)[1]), "r"((a)[2]), "r"((a)[3]), \
                   "r"((b)[0]), "r"((b)[1]))

__device__ __forceinline__ void split2(float x, float y, uint32_t& hi, uint32_t& lo) {
    __nv_bfloat162 h = __floats2bfloat162_rn(x, y);
    float rx = x - __bfloat162float(h.x);
    float ry = y - __bfloat162float(h.y);
    __nv_bfloat162 l = __floats2bfloat162_rn(rx, ry);
    hi = *(uint32_t*)&h;
    lo = *(uint32_t*)&l;
}

// ---------------- 0) fp32 -> bf16 hi/lo plane split ----------------
__global__ void split_kernel(const float* __restrict__ in,
                             uint32_t* __restrict__ hi,
                             uint32_t* __restrict__ lo, int n4) {
    int i = blockIdx.x * blockDim.x + threadIdx.x;
    if (i >= n4) return;
    float4 v = ((const float4*)in)[i];
    uint32_t h0, l0, h1, l1;
    split2(v.x, v.y, h0, l0);
    split2(v.z, v.w, h1, l1);
    ((uint2*)hi)[i] = make_uint2(h0, h1);
    ((uint2*)lo)[i] = make_uint2(l0, l1);
}

// ---------------- 1) cluster argmax: one warp per token, float4 ILP ----------------
__global__ void assign_kernel(const float* __restrict__ X,
                              const float* __restrict__ Wc,
                              const float* __restrict__ bc) {
    int gw   = (blockIdx.x * blockDim.x + threadIdx.x) >> 5;
    int lane = threadIdx.x & 31;
    if (gw >= BT_) return;
    const float4* x4 = (const float4*)(X + (size_t)gw * D_);
    float acc[C_];
#pragma unroll
    for (int c = 0; c < C_; c++) acc[c] = 0.f;
#pragma unroll
    for (int it = 0; it < 4; it++) {
        int i = it * 32 + lane;
        float4 xv = x4[i];
#pragma unroll
        for (int c = 0; c < C_; c++) {
            float4 wv = ((const float4*)(Wc + (size_t)c * D_))[i];
            float s = fmaf(xv.x, wv.x, fmaf(xv.y, wv.y, fmaf(xv.z, wv.z, xv.w * wv.w)));
            acc[c] += s;
        }
    }
#pragma unroll
    for (int c = 0; c < C_; c++)
#pragma unroll
        for (int o = 16; o; o >>= 1) acc[c] += __shfl_xor_sync(0xffffffffu, acc[c], o);
    if (lane == 0) {
        float best = acc[0] + bc[0];
        int bi = 0;
#pragma unroll
        for (int c = 1; c < C_; c++) {
            float v = acc[c] + bc[c];
            if (v > best) { best = v; bi = c; }
        }
        g_assign[gw] = bi;
    }
}

// ---------------- 2) deterministic per-(b,c) token lists (ballot scan) ----------------
__global__ __launch_bounds__(1024) void build_lists_kernel() {
    int b = blockIdx.x / C_, c = blockIdx.x % C_;
    __shared__ int wtot[32];
    const int tid = threadIdx.x, lane = tid & 31, wid = tid >> 5;
    int p = (g_assign[b * T_ + tid] == c) ? 1 : 0;
    unsigned msk = __ballot_sync(0xffffffffu, p);
    int pre = __popc(msk & ((1u << lane) - 1u));
    if (lane == 0) wtot[wid] = __popc(msk);
    __syncthreads();
    if (wid == 0) {
        int v = wtot[lane], s = v;
#pragma unroll
        for (int o = 1; o < 32; o <<= 1) {
            int u = __shfl_up_sync(0xffffffffu, s, o);
            if (lane >= o) s += u;
        }
        wtot[lane] = s - v;
        if (lane == 31) g_counts[b * C_ + c] = s;
    }
    __syncthreads();
    if (p) g_idx[(b * C_ + c) * T_ + wtot[wid] + pre] = tid;
}

// ---------------- 3/5) 3xBF16 mma.sync NT GEMM on pre-split planes, 2 CTA/SM ----------------
#define ROWW   20
#define PLANEW (128 * ROWW)
#define STAGEW (4 * PLANEW)
#define GEMM_SMEM (2 * STAGEW * 4)

__global__ __launch_bounds__(256, 2) void gemm_mma(const uint32_t* __restrict__ Ah_g,
                                                   const uint32_t* __restrict__ Al_g,
                                                   const uint32_t* __restrict__ Bh_g,
                                                   const uint32_t* __restrict__ Bl_g,
                                                   const float* __restrict__ bias,
                                                   float* __restrict__ Cm,
                                                   int M, int N, int K) {
    extern __shared__ uint32_t smw[];
    const int tid = threadIdx.x, lane = tid & 31, w = tid >> 5;
    const int wm = w & 1, wn = w >> 1;
    const int qr = lane >> 2, qc = lane & 3;
    const int m0 = blockIdx.y * 128, n0 = blockIdx.x * 128;
    const int Kw = K >> 1;

    const int lr = tid >> 1, lkw = (tid & 1) * 8;
    const uint32_t* Ahp = Ah_g + (size_t)(m0 + lr) * Kw + lkw;
    const uint32_t* Alp = Al_g + (size_t)(m0 + lr) * Kw + lkw;
    const uint32_t* Bhp = Bh_g + (size_t)(n0 + lr) * Kw + lkw;
    const uint32_t* Blp = Bl_g + (size_t)(n0 + lr) * Kw + lkw;

    float acc[4][4][4];
#pragma unroll
    for (int i = 0; i < 4; i++)
#pragma unroll
        for (int j = 0; j < 4; j++)
#pragma unroll
            for (int e = 0; e < 4; e++) acc[i][j][e] = 0.f;

    uint4 rah[2], ral[2], rbh[2], rbl[2];
    auto ldg = [&](int k0w) {
        rah[0] = *(const uint4*)(Ahp + k0w);
        rah[1] = *(const uint4*)(Ahp + k0w + 4);
        ral[0] = *(const uint4*)(Alp + k0w);
        ral[1] = *(const uint4*)(Alp + k0w + 4);
        rbh[0] = *(const uint4*)(Bhp + k0w);
        rbh[1] = *(const uint4*)(Bhp + k0w + 4);
        rbl[0] = *(const uint4*)(Blp + k0w);
        rbl[1] = *(const uint4*)(Blp + k0w + 4);
    };
    auto sts = [&](int s) {
        uint32_t* stg = smw + s * STAGEW;
        const int base = lr * ROWW + lkw;
        *(uint4*)(stg + base)                  = rah[0];
        *(uint4*)(stg + base + 4)              = rah[1];
        *(uint4*)(stg + PLANEW + base)         = ral[0];
        *(uint4*)(stg + PLANEW + base + 4)     = ral[1];
        *(uint4*)(stg + 2 * PLANEW + base)     = rbh[0];
        *(uint4*)(stg + 2 * PLANEW + base + 4) = rbh[1];
        *(uint4*)(stg + 3 * PLANEW + base)     = rbl[0];
        *(uint4*)(stg + 3 * PLANEW + base + 4) = rbl[1];
    };
    auto compute = [&](int s) {
        const uint32_t* Ah = smw + s * STAGEW;
        const uint32_t* Al = Ah + PLANEW;
        const uint32_t* Bh = Al + PLANEW;
        const uint32_t* Bl = Bh + PLANEW;
#pragma unroll
        for (int ks = 0; ks < 2; ks++) {
            const int kw = ks * 8 + qc;
            uint32_t ah[4][4], al[4][4], bh[4][2], bl[4][2];
#pragma unroll
            for (int mt = 0; mt < 4; mt++) {
                int r0w = (wm * 64 + mt * 16 + qr) * ROWW + kw;
                int r1w = r0w + 8 * ROWW;
                ah[mt][0] = Ah[r0w];     ah[mt][1] = Ah[r1w];
                ah[mt][2] = Ah[r0w + 4]; ah[mt][3] = Ah[r1w + 4];
                al[mt][0] = Al[r0w];     al[mt][1] = Al[r1w];
                al[mt][2] = Al[r0w + 4]; al[mt][3] = Al[r1w + 4];
            }
#pragma unroll
            for (int nt = 0; nt < 4; nt++) {
                int c0w = (wn * 32 + nt * 8 + qr) * ROWW + kw;
                bh[nt][0] = Bh[c0w]; bh[nt][1] = Bh[c0w + 4];
                bl[nt][0] = Bl[c0w]; bl[nt][1] = Bl[c0w + 4];
            }
#pragma unroll
            for (int mt = 0; mt < 4; mt++)
#pragma unroll
                for (int nt = 0; nt < 4; nt++) {
                    MMA_BF16(acc[mt][nt], ah[mt], bh[nt]);
                    MMA_BF16(acc[mt][nt], ah[mt], bl[nt]);
                    MMA_BF16(acc[mt][nt], al[mt], bh[nt]);
                }
        }
    };

    const int nch = K >> 5;
    ldg(0);
    sts(0);
    __syncthreads();
    for (int ch = 0; ch < nch; ch++) {
        int s = ch & 1;
        if (ch + 1 < nch) ldg((ch + 1) * 16);
        compute(s);
        if (ch + 1 < nch) sts(s ^ 1);
        __syncthreads();
    }

#pragma unroll
    for (int mt = 0; mt < 4; mt++) {
        int r = m0 + wm * 64 + mt * 16 + qr;
#pragma unroll
        for (int nt = 0; nt < 4; nt++) {
            int cc = n0 + wn * 32 + nt * 8 + 2 * qc;
            float b0 = bias[cc], b1 = bias[cc + 1];
            *(float2*)(Cm + (size_t)r * N + cc) =
                make_float2(acc[mt][nt][0] + b0, acc[mt][nt][1] + b1);
            *(float2*)(Cm + (size_t)(r + 8) * N + cc) =
                make_float2(acc[mt][nt][2] + b0, acc[mt][nt][3] + b1);
        }
    }
}

// ---------------- 4) 3xBF16 mma flash attention; epilogue writes bf16 planes ----------------
#define AST 36
#define ATTN_SMEM ((1024 + 128 + 2*128*AST + 4*64*AST) * 4)

__global__ __launch_bounds__(256) void attn_kernel(const float* __restrict__ bin) {
    extern __shared__ uint32_t smu[];
    int*      s_idx = (int*)smu;
    float*    ph    = (float*)(smu + 1024);
    uint32_t* Qh = smu + 1024 + 128;
    uint32_t* Ql = Qh + 128 * AST;
    uint32_t* Kh = Ql + 128 * AST;
    uint32_t* Kl = Kh + 64 * AST;
    uint32_t* Vh = Kl + 64 * AST;
    uint32_t* Vl = Vh + 64 * AST;

    const int bid = blockIdx.x;
    const int h = bid & 7;
    const int c = (bid >> 3) & 7;
    const int b = bid >> 6;
    const int n = g_counts[b * C_ + c];
    const int qt = blockIdx.y * 128;
    if (qt >= n) return;
    const int* idx = g_idx + (b * C_ + c) * T_;
    const int tid = threadIdx.x;
    for (int i = tid; i < n; i += 256) s_idx[i] = idx[i];
    __syncthreads();

    const float w0 = (float)(T_ - n);
    const float* bk = bin + D_     + h * HD_;
    const float* bv = bin + 2 * D_ + h * HD_;
    const int w = tid >> 5, lane = tid & 31;
    const int qr = lane >> 2, qc = lane & 3;

    {
        const int r = tid >> 1, hf = (tid & 1) * 32;
        const int wb = r * AST + hf / 2;
        float pacc = 0.f;
        int qi = qt + r;
        if (qi < n) {
            const float* qp = g_qkv + (size_t)(b * T_ + s_idx[qi]) * TD3_ + h * HD_ + hf;
#pragma unroll
            for (int j4 = 0; j4 < 8; j4++) {
                float4 v = ((const float4*)qp)[j4];
                v.x *= 0.125f; v.y *= 0.125f; v.z *= 0.125f; v.w *= 0.125f;
                uint32_t hh, ll;
                split2(v.x, v.y, hh, ll);
                Qh[wb + 2 * j4] = hh; Ql[wb + 2 * j4] = ll;
                split2(v.z, v.w, hh, ll);
                Qh[wb + 2 * j4 + 1] = hh; Ql[wb + 2 * j4 + 1] = ll;
                int d = hf + 4 * j4;
                pacc = fmaf(v.x, bk[d], pacc);
                pacc = fmaf(v.y, bk[d + 1], pacc);
                pacc = fmaf(v.z, bk[d + 2], pacc);
                pacc = fmaf(v.w, bk[d + 3], pacc);
            }
        } else {
#pragma unroll
            for (int j = 0; j < 16; j++) { Qh[wb + j] = 0u; Ql[wb + j] = 0u; }
        }
        pacc += __shfl_xor_sync(0xffffffffu, pacc, 1);
        if ((tid & 1) == 0) ph[r] = pacc;
    }
    __syncthreads();

    uint32_t qfh[16], qfl[16];
#pragma unroll
    for (int ks = 0; ks < 4; ks++) {
        int a0 = (w * 16 + qr) * AST + ks * 8 + qc;
        int a1 = a0 + 8 * AST;
        qfh[ks * 4 + 0] = Qh[a0];     qfh[ks * 4 + 1] = Qh[a1];
        qfh[ks * 4 + 2] = Qh[a0 + 4]; qfh[ks * 4 + 3] = Qh[a1 + 4];
        qfl[ks * 4 + 0] = Ql[a0];     qfl[ks * 4 + 1] = Ql[a1];
        qfl[ks * 4 + 2] = Ql[a0 + 4]; qfl[ks * 4 + 3] = Ql[a1 + 4];
    }

    float m0 = ph[w * 16 + qr], m1 = ph[w * 16 + qr + 8];
    float l0 = w0, l1 = w0;
    float O[8][4];
#pragma unroll
    for (int dnt = 0; dnt < 8; dnt++) {
        int col = dnt * 8 + 2 * qc;
        O[dnt][0] = w0 * bv[col];
        O[dnt][1] = w0 * bv[col + 1];
        O[dnt][2] = O[dnt][0];
        O[dnt][3] = O[dnt][1];
    }

    for (int kt = 0; kt < n; kt += 64) {
        const int nk = min(64, n - kt);
        __syncthreads();
        {
            const int tk = tid >> 2, dq = (tid & 3) * 16;
            const int wb = tk * AST + dq / 2;
            if (kt + tk < n) {
                const float* kp = g_qkv + (size_t)(b * T_ + s_idx[kt + tk]) * TD3_ + D_ + h * HD_ + dq;
#pragma unroll
                for (int j4 = 0; j4 < 4; j4++) {
                    float4 v = ((const float4*)kp)[j4];
                    uint32_t hh, ll;
                    split2(v.x, v.y, hh, ll);
                    Kh[wb + 2 * j4] = hh; Kl[wb + 2 * j4] = ll;
                    split2(v.z, v.w, hh, ll);
                    Kh[wb + 2 * j4 + 1] = hh; Kl[wb + 2 * j4 + 1] = ll;
                }
            } else {
#pragma unroll
                for (int j = 0; j < 8; j++) { Kh[wb + j] = 0u; Kl[wb + j] = 0u; }
            }
            __nv_bfloat16* VhB = (__nv_bfloat16*)Vh;
            __nv_bfloat16* VlB = (__nv_bfloat16*)Vl;
            if (kt + tk < n) {
                const float* vp = g_qkv + (size_t)(b * T_ + s_idx[kt + tk]) * TD3_ + 2 * D_ + h * HD_ + dq;
#pragma unroll
                for (int j4 = 0; j4 < 4; j4++) {
                    float4 v = ((const float4*)vp)[j4];
                    float vv[4] = {v.x, v.y, v.z, v.w};
#pragma unroll
                    for (int e = 0; e < 4; e++) {
                        int d = dq + 4 * j4 + e;
                        __nv_bfloat16 hh = __float2bfloat16(vv[e]);
                        VhB[d * (2 * AST) + tk] = hh;
                        VlB[d * (2 * AST) + tk] = __float2bfloat16(vv[e] - __bfloat162float(hh));
                    }
                }
            } else {
#pragma unroll
                for (int e = 0; e < 16; e++) {
                    int d = dq + e;
                    VhB[d * (2 * AST) + tk] = __float2bfloat16(0.f);
                    VlB[d * (2 * AST) + tk] = __float2bfloat16(0.f);
                }
            }
        }
        __syncthreads();

        float S[8][4];
#pragma unroll
        for (int nt = 0; nt < 8; nt++) {
            S[nt][0] = S[nt][1] = S[nt][2] = S[nt][3] = 0.f;
            int kb = (nt * 8 + qr) * AST + qc;
#pragma unroll
            for (int ks = 0; ks < 4; ks++) {
                uint32_t bh[2] = {Kh[kb + ks * 8], Kh[kb + ks * 8 + 4]};
                uint32_t bl[2] = {Kl[kb + ks * 8], Kl[kb + ks * 8 + 4]};
                MMA_BF16(S[nt], qfh + ks * 4, bh);
                MMA_BF16(S[nt], qfh + ks * 4, bl);
                MMA_BF16(S[nt], qfl + ks * 4, bh);
            }
        }

        if (nk < 64) {
#pragma unroll
            for (int nt = 0; nt < 8; nt++) {
                int c0 = nt * 8 + 2 * qc;
                if (c0 >= nk)     { S[nt][0] = -1e30f; S[nt][2] = -1e30f; }
                if (c0 + 1 >= nk) { S[nt][1] = -1e30f; S[nt][3] = -1e30f; }
            }
        }

        float r0 = -1e30f, r1 = -1e30f;
#pragma unroll
        for (int nt = 0; nt < 8; nt++) {
            r0 = fmaxf(r0, fmaxf(S[nt][0], S[nt][1]));
            r1 = fmaxf(r1, fmaxf(S[nt][2], S[nt][3]));
        }
        r0 = fmaxf(r0, __shfl_xor_sync(0xffffffffu, r0, 1));
        r0 = fmaxf(r0, __shfl_xor_sync(0xffffffffu, r0, 2));
        r1 = fmaxf(r1, __shfl_xor_sync(0xffffffffu, r1, 1));
        r1 = fmaxf(r1, __shfl_xor_sync(0xffffffffu, r1, 2));
        float mn0 = fmaxf(m0, r0), mn1 = fmaxf(m1, r1);
        float co0 = __expf(m0 - mn0), co1 = __expf(m1 - mn1);
        float s0 = 0.f, s1 = 0.f;
#pragma unroll
        for (int nt = 0; nt < 8; nt++) {
            S[nt][0] = __expf(S[nt][0] - mn0);
            S[nt][1] = __expf(S[nt][1] - mn0);
            S[nt][2] = __expf(S[nt][2] - mn1);
            S[nt][3] = __expf(S[nt][3] - mn1);
            s0 += S[nt][0] + S[nt][1];
            s1 += S[nt][2] + S[nt][3];
        }
        s0 += __shfl_xor_sync(0xffffffffu, s0, 1);
        s0 += __shfl_xor_sync(0xffffffffu, s0, 2);
        s1 += __shfl_xor_sync(0xffffffffu, s1, 1);
        s1 += __shfl_xor_sync(0xffffffffu, s1, 2);
        l0 = l0 * co0 + s0;
        l1 = l1 * co1 + s1;
        m0 = mn0; m1 = mn1;
#pragma unroll
        for (int dnt = 0; dnt < 8; dnt++) {
            O[dnt][0] *= co0; O[dnt][1] *= co0;
            O[dnt][2] *= co1; O[dnt][3] *= co1;
        }

        uint32_t pfh[16], pfl[16];
#pragma unroll
        for (int u = 0; u < 4; u++) {
            split2(S[2 * u][0],     S[2 * u][1],     pfh[u * 4 + 0], pfl[u * 4 + 0]);
            split2(S[2 * u][2],     S[2 * u][3],     pfh[u * 4 + 1], pfl[u * 4 + 1]);
            split2(S[2 * u + 1][0], S[2 * u + 1][1], pfh[u * 4 + 2], pfl[u * 4 + 2]);
            split2(S[2 * u + 1][2], S[2 * u + 1][3], pfh[u * 4 + 3], pfl[u * 4 + 3]);
        }

#pragma unroll
        for (int dnt = 0; dnt < 8; dnt++) {
            int vb = (dnt * 8 + qr) * AST + qc;
#pragma unroll
            for (int u = 0; u < 4; u++) {
                uint32_t vh[2] = {Vh[vb + u * 8], Vh[vb + u * 8 + 4]};
                uint32_t vl[2] = {Vl[vb + u * 8], Vl[vb + u * 8 + 4]};
                MMA_BF16(O[dnt], pfh + u * 4, vh);
                MMA_BF16(O[dnt], pfl + u * 4, vh);
                MMA_BF16(O[dnt], pfh + u * 4, vl);
            }
        }
    }

    // ---- normalize + split + scatter store as bf16x2 planes ----
    float i0 = 1.0f / l0, i1 = 1.0f / l1;
    int row0 = qt + w * 16 + qr;
    if (row0 < n) {
        size_t wb = (size_t)(b * T_ + s_idx[row0]) * (D_ / 2) + h * (HD_ / 2) + qc;
#pragma unroll
        for (int dnt = 0; dnt < 8; dnt++) {
            uint32_t hh, ll;
            split2(O[dnt][0] * i0, O[dnt][1] * i0, hh, ll);
            g_Oh[wb + dnt * 4] = hh;
            g_Ol[wb + dnt * 4] = ll;
        }
    }
    int row1 = row0 + 8;
    if (row1 < n) {
        size_t wb = (size_t)(b * T_ + s_idx[row1]) * (D_ / 2) + h * (HD_ / 2) + qc;
#pragma unroll
        for (int dnt = 0; dnt < 8; dnt++) {
            uint32_t hh, ll;
            split2(O[dnt][2] * i1, O[dnt][3] * i1, hh, ll);
            g_Oh[wb + dnt * 4] = hh;
            g_Ol[wb + dnt * 4] = ll;
        }
    }
}

// ---------------- launcher ----------------
extern "C" void kernel_launch(void* const* d_in, const int* in_sizes, int n_in,
                              void* d_out, int out_size) {
    const float* X    = (const float*)d_in[0];
    const float* Wc   = (const float*)d_in[1];
    const float* bc   = (const float*)d_in[2];
    const float* Win  = (const float*)d_in[3];
    const float* bin  = (const float*)d_in[4];
    const float* Wout = (const float*)d_in[5];
    const float* bout = (const float*)d_in[6];
    float* out = (float*)d_out;

    void* qkv_p = nullptr; cudaGetSymbolAddress(&qkv_p, g_qkv);
    void* Xh_p  = nullptr; cudaGetSymbolAddress(&Xh_p,  g_Xh);
    void* Xl_p  = nullptr; cudaGetSymbolAddress(&Xl_p,  g_Xl);
    void* Wih_p = nullptr; cudaGetSymbolAddress(&Wih_p, g_Wih);
    void* Wil_p = nullptr; cudaGetSymbolAddress(&Wil_p, g_Wil);
    void* Woh_p = nullptr; cudaGetSymbolAddress(&Woh_p, g_Woh);
    void* Wol_p = nullptr; cudaGetSymbolAddress(&Wol_p, g_Wol);
    void* Oh_p  = nullptr; cudaGetSymbolAddress(&Oh_p,  g_Oh);
    void* Ol_p  = nullptr; cudaGetSymbolAddress(&Ol_p,  g_Ol);

    cudaFuncSetAttribute(attn_kernel, cudaFuncAttributeMaxDynamicSharedMemorySize, ATTN_SMEM);
    cudaFuncSetAttribute(gemm_mma,    cudaFuncAttributeMaxDynamicSharedMemorySize, GEMM_SMEM);

    split_kernel<<<(BT_ * D_ / 4 + 255) / 256, 256>>>(X, (uint32_t*)Xh_p, (uint32_t*)Xl_p,
                                                      BT_ * D_ / 4);
    split_kernel<<<(TD3_ * D_ / 4 + 255) / 256, 256>>>(Win, (uint32_t*)Wih_p, (uint32_t*)Wil_p,
                                                       TD3_ * D_ / 4);
    split_kernel<<<(D_ * D_ / 4 + 255) / 256, 256>>>(Wout, (uint32_t*)Woh_p, (uint32_t*)Wol_p,
                                                     D_ * D_ / 4);
    assign_kernel<<<BT_ / 8, 256>>>(X, Wc, bc);
    build_lists_kernel<<<B_ * C_, 1024>>>();
    gemm_mma<<<dim3(TD3_ / 128, BT_ / 128), 256, GEMM_SMEM>>>(
        (const uint32_t*)Xh_p, (const uint32_t*)Xl_p,
        (const uint32_t*)Wih_p, (const uint32_t*)Wil_p,
        bin, (float*)qkv_p, BT_, TD3_, D_);
    attn_kernel<<<dim3(B_ * C_ * H_, T_ / 128), 256, ATTN_SMEM>>>(bin);
    gemm_mma<<<dim3(D_ / 128, BT_ / 128), 256, GEMM_SMEM>>>(
        (const uint32_t*)Oh_p, (const uint32_t*)Ol_p,
        (const uint32_t*)Woh_p, (const uint32_t*)Wol_p,
        bout, out, BT_, D_, D_);
}

// round 11
// speedup vs baseline: 1.8989x; 1.8989x over previous
#include <cuda_runtime.h>
#include <cuda_bf16.h>
#include <cstdint>

#define B_  4
#define T_  1024
#define D_  512
#define C_  8
#define H_  8
#define HD_ 64
#define BT_ (B_*T_)
#define TD3_ (3*D_)

// ---------------- scratch (device globals; no allocation allowed) ----------------
__device__ int   g_assign[BT_];
__device__ int   g_counts[B_*C_];
__device__ int   g_idx[B_*C_*T_];
__device__ float g_qkv[(size_t)BT_*TD3_];   // [b*T+t, 3D]  (q | k | v)
// bf16 hi/lo planes (word = bf16x2)
__device__ uint32_t g_Xh[BT_*D_/2],  g_Xl[BT_*D_/2];
__device__ uint32_t g_Wih[TD3_*D_/2], g_Wil[TD3_*D_/2];
__device__ uint32_t g_Woh[D_*D_/2],  g_Wol[D_*D_/2];
__device__ uint32_t g_Oh[BT_*D_/2],  g_Ol[BT_*D_/2];

#define MMA_BF16(d, a, b) \
    asm volatile("mma.sync.aligned.m16n8k16.row.col.f32.bf16.bf16.f32 " \
                 "{%0,%1,%2,%3},{%4,%5,%6,%7},{%8,%9},{%0,%1,%2,%3};" \
                 : "+f"((d)[0]), "+f"((d)[1]), "+f"((d)[2]), "+f"((d)[3]) \
                 : "r"((a)[0]), "r"((a)[1]), "r"((a)[2]), "r"((a)[3]), \
                   "r"((b)[0]), "r"((b)[1]))

__device__ __forceinline__ void split2(float x, float y, uint32_t& hi, uint32_t& lo) {
    __nv_bfloat162 h = __floats2bfloat162_rn(x, y);
    float rx = x - __bfloat162float(h.x);
    float ry = y - __bfloat162float(h.y);
    __nv_bfloat162 l = __floats2bfloat162_rn(rx, ry);
    hi = *(uint32_t*)&h;
    lo = *(uint32_t*)&l;
}

// ---------------- 0) fp32 -> bf16 hi/lo plane split ----------------
__global__ void split_kernel(const float* __restrict__ in,
                             uint32_t* __restrict__ hi,
                             uint32_t* __restrict__ lo, int n4) {
    int i = blockIdx.x * blockDim.x + threadIdx.x;
    if (i >= n4) return;
    float4 v = ((const float4*)in)[i];
    uint32_t h0, l0, h1, l1;
    split2(v.x, v.y, h0, l0);
    split2(v.z, v.w, h1, l1);
    ((uint2*)hi)[i] = make_uint2(h0, h1);
    ((uint2*)lo)[i] = make_uint2(l0, l1);
}

// ---------------- 1) cluster argmax: one warp per token, float4 ILP ----------------
__global__ void assign_kernel(const float* __restrict__ X,
                              const float* __restrict__ Wc,
                              const float* __restrict__ bc) {
    int gw   = (blockIdx.x * blockDim.x + threadIdx.x) >> 5;
    int lane = threadIdx.x & 31;
    if (gw >= BT_) return;
    const float4* x4 = (const float4*)(X + (size_t)gw * D_);
    float acc[C_];
#pragma unroll
    for (int c = 0; c < C_; c++) acc[c] = 0.f;
#pragma unroll
    for (int it = 0; it < 4; it++) {
        int i = it * 32 + lane;
        float4 xv = x4[i];
#pragma unroll
        for (int c = 0; c < C_; c++) {
            float4 wv = ((const float4*)(Wc + (size_t)c * D_))[i];
            float s = fmaf(xv.x, wv.x, fmaf(xv.y, wv.y, fmaf(xv.z, wv.z, xv.w * wv.w)));
            acc[c] += s;
        }
    }
#pragma unroll
    for (int c = 0; c < C_; c++)
#pragma unroll
        for (int o = 16; o; o >>= 1) acc[c] += __shfl_xor_sync(0xffffffffu, acc[c], o);
    if (lane == 0) {
        float best = acc[0] + bc[0];
        int bi = 0;
#pragma unroll
        for (int c = 1; c < C_; c++) {
            float v = acc[c] + bc[c];
            if (v > best) { best = v; bi = c; }
        }
        g_assign[gw] = bi;
    }
}

// ---------------- 2) deterministic per-(b,c) token lists (ballot scan) ----------------
__global__ __launch_bounds__(1024) void build_lists_kernel() {
    int b = blockIdx.x / C_, c = blockIdx.x % C_;
    __shared__ int wtot[32];
    const int tid = threadIdx.x, lane = tid & 31, wid = tid >> 5;
    int p = (g_assign[b * T_ + tid] == c) ? 1 : 0;
    unsigned msk = __ballot_sync(0xffffffffu, p);
    int pre = __popc(msk & ((1u << lane) - 1u));
    if (lane == 0) wtot[wid] = __popc(msk);
    __syncthreads();
    if (wid == 0) {
        int v = wtot[lane], s = v;
#pragma unroll
        for (int o = 1; o < 32; o <<= 1) {
            int u = __shfl_up_sync(0xffffffffu, s, o);
            if (lane >= o) s += u;
        }
        wtot[lane] = s - v;
        if (lane == 31) g_counts[b * C_ + c] = s;
    }
    __syncthreads();
    if (p) g_idx[(b * C_ + c) * T_ + wtot[wid] + pre] = tid;
}

// ---------------- 3/5) 3xBF16 mma.sync NT GEMM, 512 threads (16 warps 4Mx4N) ----------------
// warp tile 32x32 = 2x4 m16n8k16; pre-split bf16x2 planes; 2-stage double buffer.
#define ROWW   20
#define PLANEW (128 * ROWW)
#define STAGEW (4 * PLANEW)
#define GEMM_SMEM (2 * STAGEW * 4)

__global__ __launch_bounds__(512) void gemm_mma(const uint32_t* __restrict__ Ah_g,
                                                const uint32_t* __restrict__ Al_g,
                                                const uint32_t* __restrict__ Bh_g,
                                                const uint32_t* __restrict__ Bl_g,
                                                const float* __restrict__ bias,
                                                float* __restrict__ Cm,
                                                int M, int N, int K) {
    extern __shared__ uint32_t smw[];
    const int tid = threadIdx.x, lane = tid & 31, w = tid >> 5;
    const int wm = w & 3, wn = w >> 2;
    const int qr = lane >> 2, qc = lane & 3;
    const int m0 = blockIdx.y * 128, n0 = blockIdx.x * 128;
    const int Kw = K >> 1;

    // LDG map: row lr (0..127), 4 consecutive words at lkw
    const int lr = tid >> 2, lkw = (tid & 3) * 4;
    const uint32_t* Ahp = Ah_g + (size_t)(m0 + lr) * Kw + lkw;
    const uint32_t* Alp = Al_g + (size_t)(m0 + lr) * Kw + lkw;
    const uint32_t* Bhp = Bh_g + (size_t)(n0 + lr) * Kw + lkw;
    const uint32_t* Blp = Bl_g + (size_t)(n0 + lr) * Kw + lkw;

    float acc[2][4][4];
#pragma unroll
    for (int i = 0; i < 2; i++)
#pragma unroll
        for (int j = 0; j < 4; j++)
#pragma unroll
            for (int e = 0; e < 4; e++) acc[i][j][e] = 0.f;

    uint4 rah, ral, rbh, rbl;
    auto ldg = [&](int k0w) {
        rah = *(const uint4*)(Ahp + k0w);
        ral = *(const uint4*)(Alp + k0w);
        rbh = *(const uint4*)(Bhp + k0w);
        rbl = *(const uint4*)(Blp + k0w);
    };
    auto sts = [&](int s) {
        uint32_t* stg = smw + s * STAGEW;
        const int base = lr * ROWW + lkw;
        *(uint4*)(stg + base)              = rah;
        *(uint4*)(stg + PLANEW + base)     = ral;
        *(uint4*)(stg + 2 * PLANEW + base) = rbh;
        *(uint4*)(stg + 3 * PLANEW + base) = rbl;
    };
    auto compute = [&](int s) {
        const uint32_t* Ah = smw + s * STAGEW;
        const uint32_t* Al = Ah + PLANEW;
        const uint32_t* Bh = Al + PLANEW;
        const uint32_t* Bl = Bh + PLANEW;
#pragma unroll
        for (int ks = 0; ks < 2; ks++) {
            const int kw = ks * 8 + qc;
            uint32_t ah[2][4], al[2][4], bh[4][2], bl[4][2];
#pragma unroll
            for (int mt = 0; mt < 2; mt++) {
                int r0w = (wm * 32 + mt * 16 + qr) * ROWW + kw;
                int r1w = r0w + 8 * ROWW;
                ah[mt][0] = Ah[r0w];     ah[mt][1] = Ah[r1w];
                ah[mt][2] = Ah[r0w + 4]; ah[mt][3] = Ah[r1w + 4];
                al[mt][0] = Al[r0w];     al[mt][1] = Al[r1w];
                al[mt][2] = Al[r0w + 4]; al[mt][3] = Al[r1w + 4];
            }
#pragma unroll
            for (int nt = 0; nt < 4; nt++) {
                int c0w = (wn * 32 + nt * 8 + qr) * ROWW + kw;
                bh[nt][0] = Bh[c0w]; bh[nt][1] = Bh[c0w + 4];
                bl[nt][0] = Bl[c0w]; bl[nt][1] = Bl[c0w + 4];
            }
#pragma unroll
            for (int mt = 0; mt < 2; mt++)
#pragma unroll
                for (int nt = 0; nt < 4; nt++) {
                    MMA_BF16(acc[mt][nt], ah[mt], bh[nt]);
                    MMA_BF16(acc[mt][nt], ah[mt], bl[nt]);
                    MMA_BF16(acc[mt][nt], al[mt], bh[nt]);
                }
        }
    };

    const int nch = K >> 5;          // 16 words per chunk
    ldg(0);
    sts(0);
    __syncthreads();
    for (int ch = 0; ch < nch; ch++) {
        int s = ch & 1;
        if (ch + 1 < nch) ldg((ch + 1) * 16);
        compute(s);
        if (ch + 1 < nch) sts(s ^ 1);
        __syncthreads();
    }

#pragma unroll
    for (int mt = 0; mt < 2; mt++) {
        int r = m0 + wm * 32 + mt * 16 + qr;
#pragma unroll
        for (int nt = 0; nt < 4; nt++) {
            int cc = n0 + wn * 32 + nt * 8 + 2 * qc;
            float b0 = bias[cc], b1 = bias[cc + 1];
            *(float2*)(Cm + (size_t)r * N + cc) =
                make_float2(acc[mt][nt][0] + b0, acc[mt][nt][1] + b1);
            *(float2*)(Cm + (size_t)(r + 8) * N + cc) =
                make_float2(acc[mt][nt][2] + b0, acc[mt][nt][3] + b1);
        }
    }
}

// ---------------- 4) 3xBF16 mma flash attention; epilogue writes bf16 planes ----------------
#define AST 36
#define ATTN_SMEM ((1024 + 128 + 2*128*AST + 4*64*AST) * 4)

__global__ __launch_bounds__(256) void attn_kernel(const float* __restrict__ bin) {
    extern __shared__ uint32_t smu[];
    int*      s_idx = (int*)smu;
    float*    ph    = (float*)(smu + 1024);
    uint32_t* Qh = smu + 1024 + 128;
    uint32_t* Ql = Qh + 128 * AST;
    uint32_t* Kh = Ql + 128 * AST;
    uint32_t* Kl = Kh + 64 * AST;
    uint32_t* Vh = Kl + 64 * AST;
    uint32_t* Vl = Vh + 64 * AST;

    const int bid = blockIdx.x;
    const int h = bid & 7;
    const int c = (bid >> 3) & 7;
    const int b = bid >> 6;
    const int n = g_counts[b * C_ + c];
    const int qt = blockIdx.y * 128;
    if (qt >= n) return;
    const int* idx = g_idx + (b * C_ + c) * T_;
    const int tid = threadIdx.x;
    for (int i = tid; i < n; i += 256) s_idx[i] = idx[i];
    __syncthreads();

    const float w0 = (float)(T_ - n);
    const float* bk = bin + D_     + h * HD_;
    const float* bv = bin + 2 * D_ + h * HD_;
    const int w = tid >> 5, lane = tid & 31;
    const int qr = lane >> 2, qc = lane & 3;

    {
        const int r = tid >> 1, hf = (tid & 1) * 32;
        const int wb = r * AST + hf / 2;
        float pacc = 0.f;
        int qi = qt + r;
        if (qi < n) {
            const float* qp = g_qkv + (size_t)(b * T_ + s_idx[qi]) * TD3_ + h * HD_ + hf;
#pragma unroll
            for (int j4 = 0; j4 < 8; j4++) {
                float4 v = ((const float4*)qp)[j4];
                v.x *= 0.125f; v.y *= 0.125f; v.z *= 0.125f; v.w *= 0.125f;
                uint32_t hh, ll;
                split2(v.x, v.y, hh, ll);
                Qh[wb + 2 * j4] = hh; Ql[wb + 2 * j4] = ll;
                split2(v.z, v.w, hh, ll);
                Qh[wb + 2 * j4 + 1] = hh; Ql[wb + 2 * j4 + 1] = ll;
                int d = hf + 4 * j4;
                pacc = fmaf(v.x, bk[d], pacc);
                pacc = fmaf(v.y, bk[d + 1], pacc);
                pacc = fmaf(v.z, bk[d + 2], pacc);
                pacc = fmaf(v.w, bk[d + 3], pacc);
            }
        } else {
#pragma unroll
            for (int j = 0; j < 16; j++) { Qh[wb + j] = 0u; Ql[wb + j] = 0u; }
        }
        pacc += __shfl_xor_sync(0xffffffffu, pacc, 1);
        if ((tid & 1) == 0) ph[r] = pacc;
    }
    __syncthreads();

    uint32_t qfh[16], qfl[16];
#pragma unroll
    for (int ks = 0; ks < 4; ks++) {
        int a0 = (w * 16 + qr) * AST + ks * 8 + qc;
        int a1 = a0 + 8 * AST;
        qfh[ks * 4 + 0] = Qh[a0];     qfh[ks * 4 + 1] = Qh[a1];
        qfh[ks * 4 + 2] = Qh[a0 + 4]; qfh[ks * 4 + 3] = Qh[a1 + 4];
        qfl[ks * 4 + 0] = Ql[a0];     qfl[ks * 4 + 1] = Ql[a1];
        qfl[ks * 4 + 2] = Ql[a0 + 4]; qfl[ks * 4 + 3] = Ql[a1 + 4];
    }

    float m0 = ph[w * 16 + qr], m1 = ph[w * 16 + qr + 8];
    float l0 = w0, l1 = w0;
    float O[8][4];
#pragma unroll
    for (int dnt = 0; dnt < 8; dnt++) {
        int col = dnt * 8 + 2 * qc;
        O[dnt][0] = w0 * bv[col];
        O[dnt][1] = w0 * bv[col + 1];
        O[dnt][2] = O[dnt][0];
        O[dnt][3] = O[dnt][1];
    }

    for (int kt = 0; kt < n; kt += 64) {
        const int nk = min(64, n - kt);
        __syncthreads();
        {
            const int tk = tid >> 2, dq = (tid & 3) * 16;
            const int wb = tk * AST + dq / 2;
            if (kt + tk < n) {
                const float* kp = g_qkv + (size_t)(b * T_ + s_idx[kt + tk]) * TD3_ + D_ + h * HD_ + dq;
#pragma unroll
                for (int j4 = 0; j4 < 4; j4++) {
                    float4 v = ((const float4*)kp)[j4];
                    uint32_t hh, ll;
                    split2(v.x, v.y, hh, ll);
                    Kh[wb + 2 * j4] = hh; Kl[wb + 2 * j4] = ll;
                    split2(v.z, v.w, hh, ll);
                    Kh[wb + 2 * j4 + 1] = hh; Kl[wb + 2 * j4 + 1] = ll;
                }
            } else {
#pragma unroll
                for (int j = 0; j < 8; j++) { Kh[wb + j] = 0u; Kl[wb + j] = 0u; }
            }
            __nv_bfloat16* VhB = (__nv_bfloat16*)Vh;
            __nv_bfloat16* VlB = (__nv_bfloat16*)Vl;
            if (kt + tk < n) {
                const float* vp = g_qkv + (size_t)(b * T_ + s_idx[kt + tk]) * TD3_ + 2 * D_ + h * HD_ + dq;
#pragma unroll
                for (int j4 = 0; j4 < 4; j4++) {
                    float4 v = ((const float4*)vp)[j4];
                    float vv[4] = {v.x, v.y, v.z, v.w};
#pragma unroll
                    for (int e = 0; e < 4; e++) {
                        int d = dq + 4 * j4 + e;
                        __nv_bfloat16 hh = __float2bfloat16(vv[e]);
                        VhB[d * (2 * AST) + tk] = hh;
                        VlB[d * (2 * AST) + tk] = __float2bfloat16(vv[e] - __bfloat162float(hh));
                    }
                }
            } else {
#pragma unroll
                for (int e = 0; e < 16; e++) {
                    int d = dq + e;
                    VhB[d * (2 * AST) + tk] = __float2bfloat16(0.f);
                    VlB[d * (2 * AST) + tk] = __float2bfloat16(0.f);
                }
            }
        }
        __syncthreads();

        float S[8][4];
#pragma unroll
        for (int nt = 0; nt < 8; nt++) {
            S[nt][0] = S[nt][1] = S[nt][2] = S[nt][3] = 0.f;
            int kb = (nt * 8 + qr) * AST + qc;
#pragma unroll
            for (int ks = 0; ks < 4; ks++) {
                uint32_t bh[2] = {Kh[kb + ks * 8], Kh[kb + ks * 8 + 4]};
                uint32_t bl[2] = {Kl[kb + ks * 8], Kl[kb + ks * 8 + 4]};
                MMA_BF16(S[nt], qfh + ks * 4, bh);
                MMA_BF16(S[nt], qfh + ks * 4, bl);
                MMA_BF16(S[nt], qfl + ks * 4, bh);
            }
        }

        if (nk < 64) {
#pragma unroll
            for (int nt = 0; nt < 8; nt++) {
                int c0 = nt * 8 + 2 * qc;
                if (c0 >= nk)     { S[nt][0] = -1e30f; S[nt][2] = -1e30f; }
                if (c0 + 1 >= nk) { S[nt][1] = -1e30f; S[nt][3] = -1e30f; }
            }
        }

        float r0 = -1e30f, r1 = -1e30f;
#pragma unroll
        for (int nt = 0; nt < 8; nt++) {
            r0 = fmaxf(r0, fmaxf(S[nt][0], S[nt][1]));
            r1 = fmaxf(r1, fmaxf(S[nt][2], S[nt][3]));
        }
        r0 = fmaxf(r0, __shfl_xor_sync(0xffffffffu, r0, 1));
        r0 = fmaxf(r0, __shfl_xor_sync(0xffffffffu, r0, 2));
        r1 = fmaxf(r1, __shfl_xor_sync(0xffffffffu, r1, 1));
        r1 = fmaxf(r1, __shfl_xor_sync(0xffffffffu, r1, 2));
        float mn0 = fmaxf(m0, r0), mn1 = fmaxf(m1, r1);
        float co0 = __expf(m0 - mn0), co1 = __expf(m1 - mn1);
        float s0 = 0.f, s1 = 0.f;
#pragma unroll
        for (int nt = 0; nt < 8; nt++) {
            S[nt][0] = __expf(S[nt][0] - mn0);
            S[nt][1] = __expf(S[nt][1] - mn0);
            S[nt][2] = __expf(S[nt][2] - mn1);
            S[nt][3] = __expf(S[nt][3] - mn1);
            s0 += S[nt][0] + S[nt][1];
            s1 += S[nt][2] + S[nt][3];
        }
        s0 += __shfl_xor_sync(0xffffffffu, s0, 1);
        s0 += __shfl_xor_sync(0xffffffffu, s0, 2);
        s1 += __shfl_xor_sync(0xffffffffu, s1, 1);
        s1 += __shfl_xor_sync(0xffffffffu, s1, 2);
        l0 = l0 * co0 + s0;
        l1 = l1 * co1 + s1;
        m0 = mn0; m1 = mn1;
#pragma unroll
        for (int dnt = 0; dnt < 8; dnt++) {
            O[dnt][0] *= co0; O[dnt][1] *= co0;
            O[dnt][2] *= co1; O[dnt][3] *= co1;
        }

        uint32_t pfh[16], pfl[16];
#pragma unroll
        for (int u = 0; u < 4; u++) {
            split2(S[2 * u][0],     S[2 * u][1],     pfh[u * 4 + 0], pfl[u * 4 + 0]);
            split2(S[2 * u][2],     S[2 * u][3],     pfh[u * 4 + 1], pfl[u * 4 + 1]);
            split2(S[2 * u + 1][0], S[2 * u + 1][1], pfh[u * 4 + 2], pfl[u * 4 + 2]);
            split2(S[2 * u + 1][2], S[2 * u + 1][3], pfh[u * 4 + 3], pfl[u * 4 + 3]);
        }

#pragma unroll
        for (int dnt = 0; dnt < 8; dnt++) {
            int vb = (dnt * 8 + qr) * AST + qc;
#pragma unroll
            for (int u = 0; u < 4; u++) {
                uint32_t vh[2] = {Vh[vb + u * 8], Vh[vb + u * 8 + 4]};
                uint32_t vl[2] = {Vl[vb + u * 8], Vl[vb + u * 8 + 4]};
                MMA_BF16(O[dnt], pfh + u * 4, vh);
                MMA_BF16(O[dnt], pfl + u * 4, vh);
                MMA_BF16(O[dnt], pfh + u * 4, vl);
            }
        }
    }

    // ---- normalize + split + scatter store as bf16x2 planes ----
    float i0 = 1.0f / l0, i1 = 1.0f / l1;
    int row0 = qt + w * 16 + qr;
    if (row0 < n) {
        size_t wb = (size_t)(b * T_ + s_idx[row0]) * (D_ / 2) + h * (HD_ / 2) + qc;
#pragma unroll
        for (int dnt = 0; dnt < 8; dnt++) {
            uint32_t hh, ll;
            split2(O[dnt][0] * i0, O[dnt][1] * i0, hh, ll);
            g_Oh[wb + dnt * 4] = hh;
            g_Ol[wb + dnt * 4] = ll;
        }
    }
    int row1 = row0 + 8;
    if (row1 < n) {
        size_t wb = (size_t)(b * T_ + s_idx[row1]) * (D_ / 2) + h * (HD_ / 2) + qc;
#pragma unroll
        for (int dnt = 0; dnt < 8; dnt++) {
            uint32_t hh, ll;
            split2(O[dnt][2] * i1, O[dnt][3] * i1, hh, ll);
            g_Oh[wb + dnt * 4] = hh;
            g_Ol[wb + dnt * 4] = ll;
        }
    }
}

// ---------------- launcher ----------------
extern "C" void kernel_launch(void* const* d_in, const int* in_sizes, int n_in,
                              void* d_out, int out_size) {
    const float* X    = (const float*)d_in[0];
    const float* Wc   = (const float*)d_in[1];
    const float* bc   = (const float*)d_in[2];
    const float* Win  = (const float*)d_in[3];
    const float* bin  = (const float*)d_in[4];
    const float* Wout = (const float*)d_in[5];
    const float* bout = (const float*)d_in[6];
    float* out = (float*)d_out;

    void* qkv_p = nullptr; cudaGetSymbolAddress(&qkv_p, g_qkv);
    void* Xh_p  = nullptr; cudaGetSymbolAddress(&Xh_p,  g_Xh);
    void* Xl_p  = nullptr; cudaGetSymbolAddress(&Xl_p,  g_Xl);
    void* Wih_p = nullptr; cudaGetSymbolAddress(&Wih_p, g_Wih);
    void* Wil_p = nullptr; cudaGetSymbolAddress(&Wil_p, g_Wil);
    void* Woh_p = nullptr; cudaGetSymbolAddress(&Woh_p, g_Woh);
    void* Wol_p = nullptr; cudaGetSymbolAddress(&Wol_p, g_Wol);
    void* Oh_p  = nullptr; cudaGetSymbolAddress(&Oh_p,  g_Oh);
    void* Ol_p  = nullptr; cudaGetSymbolAddress(&Ol_p,  g_Ol);

    cudaFuncSetAttribute(attn_kernel, cudaFuncAttributeMaxDynamicSharedMemorySize, ATTN_SMEM);
    cudaFuncSetAttribute(gemm_mma,    cudaFuncAttributeMaxDynamicSharedMemorySize, GEMM_SMEM);

    split_kernel<<<(BT_ * D_ / 4 + 255) / 256, 256>>>(X, (uint32_t*)Xh_p, (uint32_t*)Xl_p,
                                                      BT_ * D_ / 4);
    split_kernel<<<(TD3_ * D_ / 4 + 255) / 256, 256>>>(Win, (uint32_t*)Wih_p, (uint32_t*)Wil_p,
                                                       TD3_ * D_ / 4);
    split_kernel<<<(D_ * D_ / 4 + 255) / 256, 256>>>(Wout, (uint32_t*)Woh_p, (uint32_t*)Wol_p,
                                                     D_ * D_ / 4);
    assign_kernel<<<BT_ / 8, 256>>>(X, Wc, bc);
    build_lists_kernel<<<B_ * C_, 1024>>>();
    gemm_mma<<<dim3(TD3_ / 128, BT_ / 128), 512, GEMM_SMEM>>>(
        (const uint32_t*)Xh_p, (const uint32_t*)Xl_p,
        (const uint32_t*)Wih_p, (const uint32_t*)Wil_p,
        bin, (float*)qkv_p, BT_, TD3_, D_);
    attn_kernel<<<dim3(B_ * C_ * H_, T_ / 128), 256, ATTN_SMEM>>>(bin);
    gemm_mma<<<dim3(D_ / 128, BT_ / 128), 512, GEMM_SMEM>>>(
        (const uint32_t*)Oh_p, (const uint32_t*)Ol_p,
        (const uint32_t*)Woh_p, (const uint32_t*)Wol_p,
        bout, out, BT_, D_, D_);
}

// round 13
// speedup vs baseline: 1.9281x; 1.0154x over previous
#include <cuda_runtime.h>
#include <cuda_bf16.h>
#include <cstdint>

#define B_  4
#define T_  1024
#define D_  512
#define C_  8
#define H_  8
#define HD_ 64
#define BT_ (B_*T_)
#define TD3_ (3*D_)

// ---------------- scratch (device globals; no allocation allowed) ----------------
__device__ int   g_assign[BT_];
__device__ int   g_counts[B_*C_];
__device__ int   g_idx[B_*C_*T_];
__device__ float g_qkv[(size_t)BT_*TD3_];   // [b*T+t, 3D]  (q | k | v)
// bf16 hi/lo planes (word = bf16x2)
__device__ uint32_t g_Xh[BT_*D_/2],  g_Xl[BT_*D_/2];
__device__ uint32_t g_Wih[TD3_*D_/2], g_Wil[TD3_*D_/2];
__device__ uint32_t g_Woh[D_*D_/2],  g_Wol[D_*D_/2];
__device__ uint32_t g_Oh[BT_*D_/2],  g_Ol[BT_*D_/2];

#define MMA_BF16(d, a, b) \
    asm volatile("mma.sync.aligned.m16n8k16.row.col.f32.bf16.bf16.f32 " \
                 "{%0,%1,%2,%3},{%4,%5,%6,%7},{%8,%9},{%0,%1,%2,%3};" \
                 : "+f"((d)[0]), "+f"((d)[1]), "+f"((d)[2]), "+f"((d)[3]) \
                 : "r"((a)[0]), "r"((a)[1]), "r"((a)[2]), "r"((a)[3]), \
                   "r"((b)[0]), "r"((b)[1]))

__device__ __forceinline__ void split2(float x, float y, uint32_t& hi, uint32_t& lo) {
    __nv_bfloat162 h = __floats2bfloat162_rn(x, y);
    float rx = x - __bfloat162float(h.x);
    float ry = y - __bfloat162float(h.y);
    __nv_bfloat162 l = __floats2bfloat162_rn(rx, ry);
    hi = *(uint32_t*)&h;
    lo = *(uint32_t*)&l;
}

// ---------------- 0) weights fp32 -> bf16 hi/lo planes (Win + Wout, one launch) ----
#define WIN4  (TD3_*D_/4)
#define WOUT4 (D_*D_/4)
__global__ void split_w_kernel(const float* __restrict__ Win,
                               const float* __restrict__ Wout) {
    int i = blockIdx.x * blockDim.x + threadIdx.x;
    const float* src;
    uint32_t *hi, *lo;
    int j;
    if (i < WIN4) { src = Win;  hi = g_Wih; lo = g_Wil; j = i; }
    else if (i < WIN4 + WOUT4) { src = Wout; hi = g_Woh; lo = g_Wol; j = i - WIN4; }
    else return;
    float4 v = ((const float4*)src)[j];
    uint32_t h0, l0, h1, l1;
    split2(v.x, v.y, h0, l0);
    split2(v.z, v.w, h1, l1);
    ((uint2*)hi)[j] = make_uint2(h0, h1);
    ((uint2*)lo)[j] = make_uint2(l0, l1);
}

// ---------------- 1) fused: cluster argmax + X split (warp per token) ----------------
__global__ void assign_splitx_kernel(const float* __restrict__ X,
                                     const float* __restrict__ Wc,
                                     const float* __restrict__ bc) {
    int gw   = (blockIdx.x * blockDim.x + threadIdx.x) >> 5;
    int lane = threadIdx.x & 31;
    if (gw >= BT_) return;
    const float4* x4 = (const float4*)(X + (size_t)gw * D_);
    uint2* xh = (uint2*)g_Xh + (size_t)gw * 128;
    uint2* xl = (uint2*)g_Xl + (size_t)gw * 128;
    float acc[C_];
#pragma unroll
    for (int c = 0; c < C_; c++) acc[c] = 0.f;
#pragma unroll
    for (int it = 0; it < 4; it++) {
        int i = it * 32 + lane;
        float4 xv = x4[i];
        // split + store planes
        uint32_t h0, l0, h1, l1;
        split2(xv.x, xv.y, h0, l0);
        split2(xv.z, xv.w, h1, l1);
        xh[i] = make_uint2(h0, h1);
        xl[i] = make_uint2(l0, l1);
        // cluster dots
#pragma unroll
        for (int c = 0; c < C_; c++) {
            float4 wv = ((const float4*)(Wc + (size_t)c * D_))[i];
            float s = fmaf(xv.x, wv.x, fmaf(xv.y, wv.y, fmaf(xv.z, wv.z, xv.w * wv.w)));
            acc[c] += s;
        }
    }
#pragma unroll
    for (int c = 0; c < C_; c++)
#pragma unroll
        for (int o = 16; o; o >>= 1) acc[c] += __shfl_xor_sync(0xffffffffu, acc[c], o);
    if (lane == 0) {
        float best = acc[0] + bc[0];
        int bi = 0;
#pragma unroll
        for (int c = 1; c < C_; c++) {
            float v = acc[c] + bc[c];
            if (v > best) { best = v; bi = c; }
        }
        g_assign[gw] = bi;
    }
}

// ---------------- 2) deterministic per-(b,c) token lists (ballot scan) ----------------
__global__ __launch_bounds__(1024) void build_lists_kernel() {
    int b = blockIdx.x / C_, c = blockIdx.x % C_;
    __shared__ int wtot[32];
    const int tid = threadIdx.x, lane = tid & 31, wid = tid >> 5;
    int p = (g_assign[b * T_ + tid] == c) ? 1 : 0;
    unsigned msk = __ballot_sync(0xffffffffu, p);
    int pre = __popc(msk & ((1u << lane) - 1u));
    if (lane == 0) wtot[wid] = __popc(msk);
    __syncthreads();
    if (wid == 0) {
        int v = wtot[lane], s = v;
#pragma unroll
        for (int o = 1; o < 32; o <<= 1) {
            int u = __shfl_up_sync(0xffffffffu, s, o);
            if (lane >= o) s += u;
        }
        wtot[lane] = s - v;
        if (lane == 31) g_counts[b * C_ + c] = s;
    }
    __syncthreads();
    if (p) g_idx[(b * C_ + c) * T_ + wtot[wid] + pre] = tid;
}

// ---------------- 3/5) 3xBF16 mma.sync NT GEMM, 512 threads (16 warps 4Mx4N) ----------------
#define ROWW   20
#define PLANEW (128 * ROWW)
#define STAGEW (4 * PLANEW)
#define GEMM_SMEM (2 * STAGEW * 4)

__global__ __launch_bounds__(512) void gemm_mma(const uint32_t* __restrict__ Ah_g,
                                                const uint32_t* __restrict__ Al_g,
                                                const uint32_t* __restrict__ Bh_g,
                                                const uint32_t* __restrict__ Bl_g,
                                                const float* __restrict__ bias,
                                                float* __restrict__ Cm,
                                                int M, int N, int K) {
    extern __shared__ uint32_t smw[];
    const int tid = threadIdx.x, lane = tid & 31, w = tid >> 5;
    const int wm = w & 3, wn = w >> 2;
    const int qr = lane >> 2, qc = lane & 3;
    const int m0 = blockIdx.y * 128, n0 = blockIdx.x * 128;
    const int Kw = K >> 1;

    const int lr = tid >> 2, lkw = (tid & 3) * 4;
    const uint32_t* Ahp = Ah_g + (size_t)(m0 + lr) * Kw + lkw;
    const uint32_t* Alp = Al_g + (size_t)(m0 + lr) * Kw + lkw;
    const uint32_t* Bhp = Bh_g + (size_t)(n0 + lr) * Kw + lkw;
    const uint32_t* Blp = Bl_g + (size_t)(n0 + lr) * Kw + lkw;

    float acc[2][4][4];
#pragma unroll
    for (int i = 0; i < 2; i++)
#pragma unroll
        for (int j = 0; j < 4; j++)
#pragma unroll
            for (int e = 0; e < 4; e++) acc[i][j][e] = 0.f;

    uint4 rah, ral, rbh, rbl;
    auto ldg = [&](int k0w) {
        rah = *(const uint4*)(Ahp + k0w);
        ral = *(const uint4*)(Alp + k0w);
        rbh = *(const uint4*)(Bhp + k0w);
        rbl = *(const uint4*)(Blp + k0w);
    };
    auto sts = [&](int s) {
        uint32_t* stg = smw + s * STAGEW;
        const int base = lr * ROWW + lkw;
        *(uint4*)(stg + base)              = rah;
        *(uint4*)(stg + PLANEW + base)     = ral;
        *(uint4*)(stg + 2 * PLANEW + base) = rbh;
        *(uint4*)(stg + 3 * PLANEW + base) = rbl;
    };
    auto compute = [&](int s) {
        const uint32_t* Ah = smw + s * STAGEW;
        const uint32_t* Al = Ah + PLANEW;
        const uint32_t* Bh = Al + PLANEW;
        const uint32_t* Bl = Bh + PLANEW;
#pragma unroll
        for (int ks = 0; ks < 2; ks++) {
            const int kw = ks * 8 + qc;
            uint32_t ah[2][4], al[2][4], bh[4][2], bl[4][2];
#pragma unroll
            for (int mt = 0; mt < 2; mt++) {
                int r0w = (wm * 32 + mt * 16 + qr) * ROWW + kw;
                int r1w = r0w + 8 * ROWW;
                ah[mt][0] = Ah[r0w];     ah[mt][1] = Ah[r1w];
                ah[mt][2] = Ah[r0w + 4]; ah[mt][3] = Ah[r1w + 4];
                al[mt][0] = Al[r0w];     al[mt][1] = Al[r1w];
                al[mt][2] = Al[r0w + 4]; al[mt][3] = Al[r1w + 4];
            }
#pragma unroll
            for (int nt = 0; nt < 4; nt++) {
                int c0w = (wn * 32 + nt * 8 + qr) * ROWW + kw;
                bh[nt][0] = Bh[c0w]; bh[nt][1] = Bh[c0w + 4];
                bl[nt][0] = Bl[c0w]; bl[nt][1] = Bl[c0w + 4];
            }
#pragma unroll
            for (int mt = 0; mt < 2; mt++)
#pragma unroll
                for (int nt = 0; nt < 4; nt++) {
                    MMA_BF16(acc[mt][nt], ah[mt], bh[nt]);
                    MMA_BF16(acc[mt][nt], ah[mt], bl[nt]);
                    MMA_BF16(acc[mt][nt], al[mt], bh[nt]);
                }
        }
    };

    const int nch = K >> 5;
    ldg(0);
    sts(0);
    __syncthreads();
    for (int ch = 0; ch < nch; ch++) {
        int s = ch & 1;
        if (ch + 1 < nch) ldg((ch + 1) * 16);
        compute(s);
        if (ch + 1 < nch) sts(s ^ 1);
        __syncthreads();
    }

#pragma unroll
    for (int mt = 0; mt < 2; mt++) {
        int r = m0 + wm * 32 + mt * 16 + qr;
#pragma unroll
        for (int nt = 0; nt < 4; nt++) {
            int cc = n0 + wn * 32 + nt * 8 + 2 * qc;
            float b0 = bias[cc], b1 = bias[cc + 1];
            *(float2*)(Cm + (size_t)r * N + cc) =
                make_float2(acc[mt][nt][0] + b0, acc[mt][nt][1] + b1);
            *(float2*)(Cm + (size_t)(r + 8) * N + cc) =
                make_float2(acc[mt][nt][2] + b0, acc[mt][nt][3] + b1);
        }
    }
}

// ---------------- 4) 3xBF16 mma flash attention; V columns permuted for LDS.64 ----------------
#define AST 36
#define ATTN_SMEM ((1024 + 128 + 2*128*AST + 4*64*AST) * 4)

__global__ __launch_bounds__(256) void attn_kernel(const float* __restrict__ bin) {
    extern __shared__ uint32_t smu[];
    int*      s_idx = (int*)smu;
    float*    ph    = (float*)(smu + 1024);
    uint32_t* Qh = smu + 1024 + 128;
    uint32_t* Ql = Qh + 128 * AST;
    uint32_t* Kh = Ql + 128 * AST;
    uint32_t* Kl = Kh + 64 * AST;
    uint32_t* Vh = Kl + 64 * AST;
    uint32_t* Vl = Vh + 64 * AST;

    const int bid = blockIdx.x;
    const int h = bid & 7;
    const int c = (bid >> 3) & 7;
    const int b = bid >> 6;
    const int n = g_counts[b * C_ + c];
    const int qt = blockIdx.y * 128;
    if (qt >= n) return;
    const int* idx = g_idx + (b * C_ + c) * T_;
    const int tid = threadIdx.x;
    for (int i = tid; i < n; i += 256) s_idx[i] = idx[i];
    __syncthreads();

    const float w0 = (float)(T_ - n);
    const float* bk = bin + D_     + h * HD_;
    const float* bv = bin + 2 * D_ + h * HD_;
    const int w = tid >> 5, lane = tid & 31;
    const int qr = lane >> 2, qc = lane & 3;

    {
        const int r = tid >> 1, hf = (tid & 1) * 32;
        const int wb = r * AST + hf / 2;
        float pacc = 0.f;
        int qi = qt + r;
        if (qi < n) {
            const float* qp = g_qkv + (size_t)(b * T_ + s_idx[qi]) * TD3_ + h * HD_ + hf;
#pragma unroll
            for (int j4 = 0; j4 < 8; j4++) {
                float4 v = ((const float4*)qp)[j4];
                v.x *= 0.125f; v.y *= 0.125f; v.z *= 0.125f; v.w *= 0.125f;
                uint32_t hh, ll;
                split2(v.x, v.y, hh, ll);
                Qh[wb + 2 * j4] = hh; Ql[wb + 2 * j4] = ll;
                split2(v.z, v.w, hh, ll);
                Qh[wb + 2 * j4 + 1] = hh; Ql[wb + 2 * j4 + 1] = ll;
                int d = hf + 4 * j4;
                pacc = fmaf(v.x, bk[d], pacc);
                pacc = fmaf(v.y, bk[d + 1], pacc);
                pacc = fmaf(v.z, bk[d + 2], pacc);
                pacc = fmaf(v.w, bk[d + 3], pacc);
            }
        } else {
#pragma unroll
            for (int j = 0; j < 16; j++) { Qh[wb + j] = 0u; Ql[wb + j] = 0u; }
        }
        pacc += __shfl_xor_sync(0xffffffffu, pacc, 1);
        if ((tid & 1) == 0) ph[r] = pacc;
    }
    __syncthreads();

    uint32_t qfh[16], qfl[16];
#pragma unroll
    for (int ks = 0; ks < 4; ks++) {
        int a0 = (w * 16 + qr) * AST + ks * 8 + qc;
        int a1 = a0 + 8 * AST;
        qfh[ks * 4 + 0] = Qh[a0];     qfh[ks * 4 + 1] = Qh[a1];
        qfh[ks * 4 + 2] = Qh[a0 + 4]; qfh[ks * 4 + 3] = Qh[a1 + 4];
        qfl[ks * 4 + 0] = Ql[a0];     qfl[ks * 4 + 1] = Ql[a1];
        qfl[ks * 4 + 2] = Ql[a0 + 4]; qfl[ks * 4 + 3] = Ql[a1 + 4];
    }

    float m0 = ph[w * 16 + qr], m1 = ph[w * 16 + qr + 8];
    float l0 = w0, l1 = w0;
    float O[8][4];
#pragma unroll
    for (int dnt = 0; dnt < 8; dnt++) {
        int col = dnt * 8 + 2 * qc;
        O[dnt][0] = w0 * bv[col];
        O[dnt][1] = w0 * bv[col + 1];
        O[dnt][2] = O[dnt][0];
        O[dnt][3] = O[dnt][1];
    }

    for (int kt = 0; kt < n; kt += 64) {
        const int nk = min(64, n - kt);
        __syncthreads();
        {
            const int tk = tid >> 2, dq = (tid & 3) * 16;
            const int wb = tk * AST + dq / 2;
            // V column permutation: logical word lw (keys 2lw,2lw+1 of group u)
            // stored at physical word u*8 + 2*(lw&3) + (lw>>2); halfword slot = key&1
            const int v_lw = (tk & 15) >> 1;
            const int v_hw = 2 * ((tk >> 4) * 8 + 2 * (v_lw & 3) + (v_lw >> 2)) + (tk & 1);
            if (kt + tk < n) {
                const float* kp = g_qkv + (size_t)(b * T_ + s_idx[kt + tk]) * TD3_ + D_ + h * HD_ + dq;
#pragma unroll
                for (int j4 = 0; j4 < 4; j4++) {
                    float4 v = ((const float4*)kp)[j4];
                    uint32_t hh, ll;
                    split2(v.x, v.y, hh, ll);
                    Kh[wb + 2 * j4] = hh; Kl[wb + 2 * j4] = ll;
                    split2(v.z, v.w, hh, ll);
                    Kh[wb + 2 * j4 + 1] = hh; Kl[wb + 2 * j4 + 1] = ll;
                }
            } else {
#pragma unroll
                for (int j = 0; j < 8; j++) { Kh[wb + j] = 0u; Kl[wb + j] = 0u; }
            }
            __nv_bfloat16* VhB = (__nv_bfloat16*)Vh;
            __nv_bfloat16* VlB = (__nv_bfloat16*)Vl;
            if (kt + tk < n) {
                const float* vp = g_qkv + (size_t)(b * T_ + s_idx[kt + tk]) * TD3_ + 2 * D_ + h * HD_ + dq;
#pragma unroll
                for (int j4 = 0; j4 < 4; j4++) {
                    float4 v = ((const float4*)vp)[j4];
                    float vv[4] = {v.x, v.y, v.z, v.w};
#pragma unroll
                    for (int e = 0; e < 4; e++) {
                        int d = dq + 4 * j4 + e;
                        __nv_bfloat16 hh = __float2bfloat16(vv[e]);
                        VhB[d * (2 * AST) + v_hw] = hh;
                        VlB[d * (2 * AST) + v_hw] = __float2bfloat16(vv[e] - __bfloat162float(hh));
                    }
                }
            } else {
#pragma unroll
                for (int e = 0; e < 16; e++) {
                    int d = dq + e;
                    VhB[d * (2 * AST) + v_hw] = __float2bfloat16(0.f);
                    VlB[d * (2 * AST) + v_hw] = __float2bfloat16(0.f);
                }
            }
        }
        __syncthreads();

        float S[8][4];
#pragma unroll
        for (int nt = 0; nt < 8; nt++) {
            S[nt][0] = S[nt][1] = S[nt][2] = S[nt][3] = 0.f;
            int kb = (nt * 8 + qr) * AST + qc;
#pragma unroll
            for (int ks = 0; ks < 4; ks++) {
                uint32_t bh[2] = {Kh[kb + ks * 8], Kh[kb + ks * 8 + 4]};
                uint32_t bl[2] = {Kl[kb + ks * 8], Kl[kb + ks * 8 + 4]};
                MMA_BF16(S[nt], qfh + ks * 4, bh);
                MMA_BF16(S[nt], qfh + ks * 4, bl);
                MMA_BF16(S[nt], qfl + ks * 4, bh);
            }
        }

        if (nk < 64) {
#pragma unroll
            for (int nt = 0; nt < 8; nt++) {
                int c0 = nt * 8 + 2 * qc;
                if (c0 >= nk)     { S[nt][0] = -1e30f; S[nt][2] = -1e30f; }
                if (c0 + 1 >= nk) { S[nt][1] = -1e30f; S[nt][3] = -1e30f; }
            }
        }

        float r0 = -1e30f, r1 = -1e30f;
#pragma unroll
        for (int nt = 0; nt < 8; nt++) {
            r0 = fmaxf(r0, fmaxf(S[nt][0], S[nt][1]));
            r1 = fmaxf(r1, fmaxf(S[nt][2], S[nt][3]));
        }
        r0 = fmaxf(r0, __shfl_xor_sync(0xffffffffu, r0, 1));
        r0 = fmaxf(r0, __shfl_xor_sync(0xffffffffu, r0, 2));
        r1 = fmaxf(r1, __shfl_xor_sync(0xffffffffu, r1, 1));
        r1 = fmaxf(r1, __shfl_xor_sync(0xffffffffu, r1, 2));
        float mn0 = fmaxf(m0, r0), mn1 = fmaxf(m1, r1);
        float co0 = __expf(m0 - mn0), co1 = __expf(m1 - mn1);
        float s0 = 0.f, s1 = 0.f;
#pragma unroll
        for (int nt = 0; nt < 8; nt++) {
            S[nt][0] = __expf(S[nt][0] - mn0);
            S[nt][1] = __expf(S[nt][1] - mn0);
            S[nt][2] = __expf(S[nt][2] - mn1);
            S[nt][3] = __expf(S[nt][3] - mn1);
            s0 += S[nt][0] + S[nt][1];
            s1 += S[nt][2] + S[nt][3];
        }
        s0 += __shfl_xor_sync(0xffffffffu, s0, 1);
        s0 += __shfl_xor_sync(0xffffffffu, s0, 2);
        s1 += __shfl_xor_sync(0xffffffffu, s1, 1);
        s1 += __shfl_xor_sync(0xffffffffu, s1, 2);
        l0 = l0 * co0 + s0;
        l1 = l1 * co1 + s1;
        m0 = mn0; m1 = mn1;
#pragma unroll
        for (int dnt = 0; dnt < 8; dnt++) {
            O[dnt][0] *= co0; O[dnt][1] *= co0;
            O[dnt][2] *= co1; O[dnt][3] *= co1;
        }

        uint32_t pfh[16], pfl[16];
#pragma unroll
        for (int u = 0; u < 4; u++) {
            split2(S[2 * u][0],     S[2 * u][1],     pfh[u * 4 + 0], pfl[u * 4 + 0]);
            split2(S[2 * u][2],     S[2 * u][3],     pfh[u * 4 + 1], pfl[u * 4 + 1]);
            split2(S[2 * u + 1][0], S[2 * u + 1][1], pfh[u * 4 + 2], pfl[u * 4 + 2]);
            split2(S[2 * u + 1][2], S[2 * u + 1][3], pfh[u * 4 + 3], pfl[u * 4 + 3]);
        }

        // O += P V; permuted layout -> each b-frag pair is one LDS.64
#pragma unroll
        for (int dnt = 0; dnt < 8; dnt++) {
            int vb2 = (dnt * 8 + qr) * AST + 2 * qc;
#pragma unroll
            for (int u = 0; u < 4; u++) {
                uint2 vhp = *(const uint2*)&Vh[vb2 + u * 8];
                uint2 vlp = *(const uint2*)&Vl[vb2 + u * 8];
                uint32_t vh[2] = {vhp.x, vhp.y};
                uint32_t vl[2] = {vlp.x, vlp.y};
                MMA_BF16(O[dnt], pfh + u * 4, vh);
                MMA_BF16(O[dnt], pfl + u * 4, vh);
                MMA_BF16(O[dnt], pfh + u * 4, vl);
            }
        }
    }

    // ---- normalize + split + scatter store as bf16x2 planes ----
    float i0 = 1.0f / l0, i1 = 1.0f / l1;
    int row0 = qt + w * 16 + qr;
    if (row0 < n) {
        size_t wb = (size_t)(b * T_ + s_idx[row0]) * (D_ / 2) + h * (HD_ / 2) + qc;
#pragma unroll
        for (int dnt = 0; dnt < 8; dnt++) {
            uint32_t hh, ll;
            split2(O[dnt][0] * i0, O[dnt][1] * i0, hh, ll);
            g_Oh[wb + dnt * 4] = hh;
            g_Ol[wb + dnt * 4] = ll;
        }
    }
    int row1 = row0 + 8;
    if (row1 < n) {
        size_t wb = (size_t)(b * T_ + s_idx[row1]) * (D_ / 2) + h * (HD_ / 2) + qc;
#pragma unroll
        for (int dnt = 0; dnt < 8; dnt++) {
            uint32_t hh, ll;
            split2(O[dnt][2] * i1, O[dnt][3] * i1, hh, ll);
            g_Oh[wb + dnt * 4] = hh;
            g_Ol[wb + dnt * 4] = ll;
        }
    }
}

// ---------------- launcher ----------------
extern "C" void kernel_launch(void* const* d_in, const int* in_sizes, int n_in,
                              void* d_out, int out_size) {
    const float* X    = (const float*)d_in[0];
    const float* Wc   = (const float*)d_in[1];
    const float* bc   = (const float*)d_in[2];
    const float* Win  = (const float*)d_in[3];
    const float* bin  = (const float*)d_in[4];
    const float* Wout = (const float*)d_in[5];
    const float* bout = (const float*)d_in[6];
    float* out = (float*)d_out;

    void* qkv_p = nullptr; cudaGetSymbolAddress(&qkv_p, g_qkv);
    void* Xh_p  = nullptr; cudaGetSymbolAddress(&Xh_p,  g_Xh);
    void* Xl_p  = nullptr; cudaGetSymbolAddress(&Xl_p,  g_Xl);
    void* Wih_p = nullptr; cudaGetSymbolAddress(&Wih_p, g_Wih);
    void* Wil_p = nullptr; cudaGetSymbolAddress(&Wil_p, g_Wil);
    void* Woh_p = nullptr; cudaGetSymbolAddress(&Woh_p, g_Woh);
    void* Wol_p = nullptr; cudaGetSymbolAddress(&Wol_p, g_Wol);
    void* Oh_p  = nullptr; cudaGetSymbolAddress(&Oh_p,  g_Oh);
    void* Ol_p  = nullptr; cudaGetSymbolAddress(&Ol_p,  g_Ol);

    cudaFuncSetAttribute(attn_kernel, cudaFuncAttributeMaxDynamicSharedMemorySize, ATTN_SMEM);
    cudaFuncSetAttribute(gemm_mma,    cudaFuncAttributeMaxDynamicSharedMemorySize, GEMM_SMEM);

    split_w_kernel<<<(WIN4 + WOUT4 + 255) / 256, 256>>>(Win, Wout);
    assign_splitx_kernel<<<BT_ / 8, 256>>>(X, Wc, bc);
    build_lists_kernel<<<B_ * C_, 1024>>>();
    gemm_mma<<<dim3(TD3_ / 128, BT_ / 128), 512, GEMM_SMEM>>>(
        (const uint32_t*)Xh_p, (const uint32_t*)Xl_p,
        (const uint32_t*)Wih_p, (const uint32_t*)Wil_p,
        bin, (float*)qkv_p, BT_, TD3_, D_);
    attn_kernel<<<dim3(B_ * C_ * H_, T_ / 128), 256, ATTN_SMEM>>>(bin);
    gemm_mma<<<dim3(D_ / 128, BT_ / 128), 512, GEMM_SMEM>>>(
        (const uint32_t*)Oh_p, (const uint32_t*)Ol_p,
        (const uint32_t*)Woh_p, (const uint32_t*)Wol_p,
        bout, out, BT_, D_, D_);
}